// round 14
// baseline (speedup 1.0000x reference)
#include <cuda_runtime.h>
#include <cuda_fp16.h>

// 5x5 median filter, reflect padding, [16,3,256,256] fp32.
//
// fp16x2 packed median, stride-2 packing P[c] = (v[c], v[c+2]) for
// c%4 in {0,1} only (34 packed cols per row; each scalar stored once).
// Round 14: packed-slot loader (2 LDG.32 + F2FP + STS.32 per slot) and a
// third elided first-layer CAS in minmax8 via a shared cas2(x2,x3).
// Column sort dedup via PRMT (r13), shared-4 selections + tournament
// extensions (r6), forgetful rank-7-of-13 (r5-r13).

#define BX 16
#define BY 16
#define PPT 4
#define OUT_W (BX * PPT)        // 64
#define OUT_H BY                // 16
#define PAD 2
#define TILE_W (OUT_W + 2*PAD)  // 68 source columns
#define TILE_H (OUT_H + 2*PAD)  // 20
#define PROW 68                 // packed-row stride in half2 (272B = 17*16B)
#define NPC 34                  // packed cols per row
#define IMG 256

__device__ __forceinline__ void cas2(__half2& a, __half2& b) {
    __half2 lo = __hmin2(a, b);
    __half2 hi = __hmax2(a, b);
    a = lo;
    b = hi;
}

// Optimal 9-CAS sorting network for 5 elements (packed).
__device__ __forceinline__ void sort5p(__half2& a, __half2& b, __half2& c,
                                       __half2& d, __half2& e) {
    cas2(a, b); cas2(d, e); cas2(c, e); cas2(c, d); cas2(b, e);
    cas2(a, d); cas2(a, c); cas2(b, d); cas2(b, c);
}

// (a.y, b.x) as a half2 — lane-wise column recombination (exact bit-moves).
__device__ __forceinline__ __half2 midcol(__half2 a, __half2 b) {
    unsigned int r = __byte_perm(*reinterpret_cast<unsigned int*>(&a),
                                 *reinterpret_cast<unsigned int*>(&b), 0x5432);
    return *reinterpret_cast<__half2*>(&r);
}

// Branch-free reflect for pad<=2 on [0,255]: -2->2, -1->1, 256->254, 257->253.
__device__ __forceinline__ int refl255(int x) {
    return 255 - abs(255 - abs(x));
}

__global__ __launch_bounds__(BX * BY, 6) void median5_kernel(
    const float* __restrict__ in, float* __restrict__ out) {
    // Packed tile: P[r][c] = (half v[c], half v[c+2]) for c%4 in {0,1}.
    __shared__ __half2 P[TILE_H][PROW];

    const int plane = blockIdx.z;  // 48 planes
    const float* src = in + (size_t)plane * IMG * IMG;
    float* dst = out + (size_t)plane * IMG * IMG;

    const int bx = blockIdx.x * OUT_W;
    const int by = blockIdx.y * OUT_H;
    const int tx = threadIdx.x;
    const int ty = threadIdx.y;

    // ---- Packed-slot halo loader ----
    // Packed col slots cp = tx, tx+16, (tx<2: tx+32); c = 4*(cp>>1)+(cp&1).
    // Slot (r, cp): P[r][c] = (v[c], v[c+2]) via 2x LDG.32 + F2FP + STS.32.
    // Row slots r = ty + 16j, j=0,1 (j=1 iff ty<4).
    {
        int cs[3], gx0[3], gx2[3];
        #pragma unroll
        for (int k = 0; k < 3; k++) {
            int cp = tx + 16 * k;
            int c = 4 * (cp >> 1) + (cp & 1);
            cs[k] = c;
            gx0[k] = refl255(bx + c - PAD);
            gx2[k] = refl255(bx + c + 2 - PAD);
        }
        int gy0 = refl255(by + ty - PAD);
        int gy1 = refl255(by + ty + 16 - PAD);

        #pragma unroll
        for (int j = 0; j < 2; j++) {
            if (j == 1 && ty >= TILE_H - 16) break;  // r < 20
            int r = ty + 16 * j;
            const float* rowsrc = src + (j == 0 ? gy0 : gy1) * IMG;
            #pragma unroll
            for (int k = 0; k < 3; k++) {
                if (k == 2 && tx >= NPC - 32) break;  // cp < 34
                P[r][cs[k]] = __floats2half2_rn(rowsrc[gx0[k]], rowsrc[gx2[k]]);
            }
        }
    }
    __syncthreads();

    // Read packed cols 0,1,4,5 (two LDS.64 per row), sort each once.
    __half2 col0[5], col1[5], col4[5], col5[5];
    #pragma unroll
    for (int r = 0; r < 5; r++) {
        const __half2* rowp = &P[ty + r][tx * PPT];
        uint2 qa = *reinterpret_cast<const uint2*>(rowp);
        uint2 qb = *reinterpret_cast<const uint2*>(rowp + 4);
        col0[r] = *reinterpret_cast<__half2*>(&qa.x);
        col1[r] = *reinterpret_cast<__half2*>(&qa.y);
        col4[r] = *reinterpret_cast<__half2*>(&qb.x);
        col5[r] = *reinterpret_cast<__half2*>(&qb.y);
    }
    sort5p(col0[0], col0[1], col0[2], col0[3], col0[4]);
    sort5p(col1[0], col1[1], col1[2], col1[3], col1[4]);
    sort5p(col4[0], col4[1], col4[2], col4[3], col4[4]);
    sort5p(col5[0], col5[1], col5[2], col5[3], col5[4]);

    // Candidate sets for the two pairs (pair 0: cols 0..4, pair 1: cols 1..5).
    // Slot layout (triple-elided minmax8 — three pre-sorted pairs):
    //   w0<=w1 : row0 (2nd max, max)
    //   w2<=w3 : row1 (third-of-top3, mx)
    //   w4<=w5 : row2 mids (x2,x3) after shared cas
    //   w6,w7  : row1 max(y,e), row2 extension (unordered)
    __half2 w[2][8], s[2][5];

    // ---- Row 0 (column minima): top-2 set of 5. ----
    {
        __half2 x1 = col1[0], x4 = col4[0];
        __half2 x2 = midcol(col0[0], col4[0]);
        __half2 x3 = midcol(col1[0], col5[0]);
        cas2(x1, x2); cas2(x3, x4);
        __half2 T1 = __hmax2(x2, x4);
        __half2 T2 = __hmax2(__hmin2(x2, x4), __hmax2(x1, x3));
        __half2 e0 = col0[0], e1 = col5[0];
        w[0][1] = __hmax2(T1, e0); w[0][0] = __hmax2(T2, __hmin2(T1, e0));
        w[1][1] = __hmax2(T1, e1); w[1][0] = __hmax2(T2, __hmin2(T1, e1));
    }
    // ---- Row 1: top-3 set of 5: {third, mx, max(y,e)}. ----
    {
        __half2 x1 = col1[1], x4 = col4[1];
        __half2 x2 = midcol(col0[1], col4[1]);
        __half2 x3 = midcol(col1[1], col5[1]);
        cas2(x1, x2); cas2(x3, x4);
        __half2 y  = __hmax2(x1, x3);
        __half2 mx = __hmax2(x2, x4), mn = __hmin2(x2, x4);
        __half2 e0 = col0[1], e1 = col5[1];
        w[0][3] = mx; w[0][6] = __hmax2(y, e0); w[0][2] = __hmax2(mn, __hmin2(y, e0));
        w[1][3] = mx; w[1][6] = __hmax2(y, e1); w[1][2] = __hmax2(mn, __hmin2(y, e1));
    }
    // ---- Row 2 (column medians): middle-3 set of 5; mids pre-sorted. ----
    {
        __half2 x1 = col1[2], x4 = col4[2];
        __half2 x2 = midcol(col0[2], col4[2]);
        __half2 x3 = midcol(col1[2], col5[2]);
        cas2(x1, x2); cas2(x3, x4); cas2(x1, x3); cas2(x2, x4);
        cas2(x2, x3);  // shared: (x2,x3) sorted for both pairs
        __half2 e0 = col0[2], e1 = col5[2];
        w[0][4] = x2; w[0][5] = x3; w[0][7] = __hmin2(__hmax2(x1, e0), x4);
        w[1][4] = x2; w[1][5] = x3; w[1][7] = __hmin2(__hmax2(x1, e1), x4);
    }
    // ---- Row 3: bottom-3 set of 5. ----
    {
        __half2 x1 = col1[3], x4 = col4[3];
        __half2 x2 = midcol(col0[3], col4[3]);
        __half2 x3 = midcol(col1[3], col5[3]);
        cas2(x1, x2); cas2(x3, x4);
        __half2 z = __hmin2(x2, x4);
        __half2 m = __hmin2(x1, x3), M = __hmax2(x1, x3);
        __half2 e0 = col0[3], e1 = col5[3];
        s[0][0] = m; s[0][1] = __hmin2(z, e0); s[0][2] = __hmin2(M, __hmax2(z, e0));
        s[1][0] = m; s[1][1] = __hmin2(z, e1); s[1][2] = __hmin2(M, __hmax2(z, e1));
    }
    // ---- Row 4 (column maxima): bottom-2 set of 5. ----
    {
        __half2 x1 = col1[4], x4 = col4[4];
        __half2 x2 = midcol(col0[4], col4[4]);
        __half2 x3 = midcol(col1[4], col5[4]);
        cas2(x1, x2); cas2(x3, x4);
        __half2 B1 = __hmin2(x1, x3);
        __half2 B2 = __hmin2(__hmax2(x1, x3), __hmin2(x2, x4));
        __half2 e0 = col0[4], e1 = col5[4];
        s[0][3] = __hmin2(B1, e0); s[0][4] = __hmin2(B2, __hmax2(B1, e0));
        s[1][3] = __hmin2(B1, e1); s[1][4] = __hmin2(B2, __hmax2(B1, e1));
    }

    // Forgetful selection: median = rank 7 (1-indexed) of the 13 candidates.
    __half2 res[2];
    #pragma unroll
    for (int g = 0; g < 2; g++) {
        __half2 w0 = w[g][0], w1 = w[g][1], w2 = w[g][2], w3 = w[g][3];
        __half2 w4 = w[g][4], w5 = w[g][5], w6 = w[g][6], w7 = w[g][7];

        // minmax8 (tree); (w0,w1),(w2,w3),(w4,w5) pre-ordered -> 7 CAS.
        cas2(w6, w7);
        cas2(w0, w2); cas2(w4, w6); cas2(w0, w4);   // w0 = min8
        cas2(w1, w3); cas2(w5, w7); cas2(w3, w7);   // w7 = max8
        w0 = s[g][0];
        // minmax7: survivors w1..w5.
        cas2(w0, w1); cas2(w2, w3); cas2(w4, w5);
        cas2(w0, w2); cas2(w4, w6); cas2(w0, w4);
        cas2(w1, w3); cas2(w5, w6); cas2(w3, w6);
        w0 = s[g][1];
        // minmax6: survivors w1..w4.
        cas2(w0, w1); cas2(w2, w3); cas2(w4, w5);
        cas2(w0, w2); cas2(w0, w4);
        cas2(w1, w3); cas2(w3, w5);
        w0 = s[g][2];
        // minmax5: survivors w1, w2, w4.
        cas2(w0, w1); cas2(w2, w3); cas2(w0, w2); cas2(w1, w3); cas2(w0, w4); cas2(w4, w3);
        w0 = s[g][3];
        // minmax4 on (w0, w1, w2, w4): survivors w1, w2.
        cas2(w0, w1); cas2(w2, w4); cas2(w0, w2); cas2(w1, w4);
        // med3(s4, w1, w2) via 4-op identity.
        __half2 a = s[g][4];
        res[g] = __hmax2(__hmin2(a, w1), __hmin2(__hmax2(a, w1), w2));
    }

    // Unpack: pair0 = pixels (0,2), pair1 = pixels (1,3).
    float2 p0 = __half22float2(res[0]);
    float2 p1 = __half22float2(res[1]);
    float4 r4 = make_float4(p0.x, p1.x, p0.y, p1.y);

    const int gy = by + ty;
    *reinterpret_cast<float4*>(&dst[gy * IMG + bx + tx * PPT]) = r4;
}

extern "C" void kernel_launch(void* const* d_in, const int* in_sizes, int n_in,
                              void* d_out, int out_size) {
    const float* image = (const float*)d_in[0];
    float* out = (float*)d_out;
    (void)in_sizes; (void)n_in; (void)out_size;

    dim3 block(BX, BY);
    dim3 grid(IMG / OUT_W, IMG / OUT_H, 16 * 3);
    median5_kernel<<<grid, block>>>(image, out);
}

// round 15
// speedup vs baseline: 1.0107x; 1.0107x over previous
#include <cuda_runtime.h>
#include <cuda_fp16.h>

// 5x5 median filter, reflect padding, [16,3,256,256] fp32.
//
// fp16x2 packed median, stride-2 packing P[c] = (v[c], v[c+2]) for
// c%4 in {0,1} only.  Round 15: vectorized group loader — group g covers
// tile cols 4g..4g+3 whose SOURCE floats are contiguous, so interior groups
// need no x-reflect: 2x LDG.64 + 2x F2FP + 1x STS.64 per (row,group).
// Only (bx==0,g==0) and (bx==192,g==16) take a scalar reflect fallback
// (owned by tx==0).  Compute: PRMT column dedup (r13), shared-4 selections
// + tournament extensions (r6), triple-elided forgetful rank-7-of-13 (r14).

#define BX 16
#define BY 16
#define PPT 4
#define OUT_W (BX * PPT)        // 64
#define OUT_H BY                // 16
#define PAD 2
#define TILE_W (OUT_W + 2*PAD)  // 68 source columns
#define TILE_H (OUT_H + 2*PAD)  // 20
#define PROW 68                 // packed-row stride in half2 (272B = 17*16B)
#define IMG 256

__device__ __forceinline__ void cas2(__half2& a, __half2& b) {
    __half2 lo = __hmin2(a, b);
    __half2 hi = __hmax2(a, b);
    a = lo;
    b = hi;
}

// Optimal 9-CAS sorting network for 5 elements (packed).
__device__ __forceinline__ void sort5p(__half2& a, __half2& b, __half2& c,
                                       __half2& d, __half2& e) {
    cas2(a, b); cas2(d, e); cas2(c, e); cas2(c, d); cas2(b, e);
    cas2(a, d); cas2(a, c); cas2(b, d); cas2(b, c);
}

// (a.y, b.x) as a half2 — lane-wise column recombination (exact bit-moves).
__device__ __forceinline__ __half2 midcol(__half2 a, __half2 b) {
    unsigned int r = __byte_perm(*reinterpret_cast<unsigned int*>(&a),
                                 *reinterpret_cast<unsigned int*>(&b), 0x5432);
    return *reinterpret_cast<__half2*>(&r);
}

// Branch-free reflect for pad<=2 on [0,255]: -2->2, -1->1, 256->254, 257->253.
__device__ __forceinline__ int refl255(int x) {
    return 255 - abs(255 - abs(x));
}

// Store packed group g (tile cols 4g..4g+3) for tile row r from 4 floats.
__device__ __forceinline__ void store_group(__half2 (*P)[PROW], int r, int g,
                                            float f0, float f1, float f2, float f3) {
    __half2 h0 = __floats2half2_rn(f0, f2);   // P[r][4g]   = (v[4g],   v[4g+2])
    __half2 h1 = __floats2half2_rn(f1, f3);   // P[r][4g+1] = (v[4g+1], v[4g+3])
    uint2 st = make_uint2(*reinterpret_cast<unsigned int*>(&h0),
                          *reinterpret_cast<unsigned int*>(&h1));
    *reinterpret_cast<uint2*>(&P[r][4 * g]) = st;
}

__global__ __launch_bounds__(BX * BY, 6) void median5_kernel(
    const float* __restrict__ in, float* __restrict__ out) {
    // Packed tile: P[r][c] = (half v[c], half v[c+2]) for c%4 in {0,1}.
    __shared__ __half2 P[TILE_H][PROW];

    const int plane = blockIdx.z;  // 48 planes
    const float* src = in + (size_t)plane * IMG * IMG;
    float* dst = out + (size_t)plane * IMG * IMG;

    const int bx = blockIdx.x * OUT_W;
    const int by = blockIdx.y * OUT_H;
    const int tx = threadIdx.x;
    const int ty = threadIdx.y;

    // ---- Vectorized group loader ----
    // 17 groups/row: g = tx (all threads) + g = 16 (tx==0).  Interior groups
    // read 4 contiguous source floats (no x-reflect).  Edge groups
    // (bx==0,g==0) and (bx==192,g==16) reflect per element.
    {
        const bool edgeL = (bx == 0);
        const bool edgeR = (bx + OUT_W == IMG);
        const int gy0 = refl255(by + ty - PAD);
        const int gy1 = refl255(by + ty + 16 - PAD);

        #pragma unroll
        for (int j = 0; j < 2; j++) {
            if (j == 1 && ty >= TILE_H - 16) break;  // r < 20
            const int r = ty + 16 * j;
            const float* rowsrc = src + (j == 0 ? gy0 : gy1) * IMG;

            // main group g = tx
            if (tx == 0 && edgeL) {
                // g = 0, source x = -2..1 -> reflect: 2,1,0,1
                store_group(P, r, 0, rowsrc[2], rowsrc[1], rowsrc[0], rowsrc[1]);
            } else {
                const float* p = rowsrc + bx + 4 * tx - PAD;
                float2 a = *reinterpret_cast<const float2*>(p);
                float2 b = *reinterpret_cast<const float2*>(p + 2);
                store_group(P, r, tx, a.x, a.y, b.x, b.y);
            }
            // extra group g = 16 (tile cols 64..67)
            if (tx == 0) {
                if (edgeR) {
                    // source x = 254..257 -> reflect: 254,255,254,253
                    store_group(P, r, 16, rowsrc[254], rowsrc[255],
                                rowsrc[254], rowsrc[253]);
                } else {
                    const float* p = rowsrc + bx + 64 - PAD;
                    float2 a = *reinterpret_cast<const float2*>(p);
                    float2 b = *reinterpret_cast<const float2*>(p + 2);
                    store_group(P, r, 16, a.x, a.y, b.x, b.y);
                }
            }
        }
    }
    __syncthreads();

    // Read packed cols 0,1,4,5 (two LDS.64 per row), sort each once.
    __half2 col0[5], col1[5], col4[5], col5[5];
    #pragma unroll
    for (int r = 0; r < 5; r++) {
        const __half2* rowp = &P[ty + r][tx * PPT];
        uint2 qa = *reinterpret_cast<const uint2*>(rowp);
        uint2 qb = *reinterpret_cast<const uint2*>(rowp + 4);
        col0[r] = *reinterpret_cast<__half2*>(&qa.x);
        col1[r] = *reinterpret_cast<__half2*>(&qa.y);
        col4[r] = *reinterpret_cast<__half2*>(&qb.x);
        col5[r] = *reinterpret_cast<__half2*>(&qb.y);
    }
    sort5p(col0[0], col0[1], col0[2], col0[3], col0[4]);
    sort5p(col1[0], col1[1], col1[2], col1[3], col1[4]);
    sort5p(col4[0], col4[1], col4[2], col4[3], col4[4]);
    sort5p(col5[0], col5[1], col5[2], col5[3], col5[4]);

    // Candidate sets for the two pairs (pair 0: cols 0..4, pair 1: cols 1..5).
    // Slot layout (triple-elided minmax8 — three pre-sorted pairs):
    //   w0<=w1 : row0 (2nd max, max)
    //   w2<=w3 : row1 (third-of-top3, mx)
    //   w4<=w5 : row2 mids (x2,x3) after shared cas
    //   w6,w7  : row1 max(y,e), row2 extension (unordered)
    __half2 w[2][8], s[2][5];

    // ---- Row 0 (column minima): top-2 set of 5. ----
    {
        __half2 x1 = col1[0], x4 = col4[0];
        __half2 x2 = midcol(col0[0], col4[0]);
        __half2 x3 = midcol(col1[0], col5[0]);
        cas2(x1, x2); cas2(x3, x4);
        __half2 T1 = __hmax2(x2, x4);
        __half2 T2 = __hmax2(__hmin2(x2, x4), __hmax2(x1, x3));
        __half2 e0 = col0[0], e1 = col5[0];
        w[0][1] = __hmax2(T1, e0); w[0][0] = __hmax2(T2, __hmin2(T1, e0));
        w[1][1] = __hmax2(T1, e1); w[1][0] = __hmax2(T2, __hmin2(T1, e1));
    }
    // ---- Row 1: top-3 set of 5: {third, mx, max(y,e)}. ----
    {
        __half2 x1 = col1[1], x4 = col4[1];
        __half2 x2 = midcol(col0[1], col4[1]);
        __half2 x3 = midcol(col1[1], col5[1]);
        cas2(x1, x2); cas2(x3, x4);
        __half2 y  = __hmax2(x1, x3);
        __half2 mx = __hmax2(x2, x4), mn = __hmin2(x2, x4);
        __half2 e0 = col0[1], e1 = col5[1];
        w[0][3] = mx; w[0][6] = __hmax2(y, e0); w[0][2] = __hmax2(mn, __hmin2(y, e0));
        w[1][3] = mx; w[1][6] = __hmax2(y, e1); w[1][2] = __hmax2(mn, __hmin2(y, e1));
    }
    // ---- Row 2 (column medians): middle-3 set of 5; mids pre-sorted. ----
    {
        __half2 x1 = col1[2], x4 = col4[2];
        __half2 x2 = midcol(col0[2], col4[2]);
        __half2 x3 = midcol(col1[2], col5[2]);
        cas2(x1, x2); cas2(x3, x4); cas2(x1, x3); cas2(x2, x4);
        cas2(x2, x3);  // shared: (x2,x3) sorted for both pairs
        __half2 e0 = col0[2], e1 = col5[2];
        w[0][4] = x2; w[0][5] = x3; w[0][7] = __hmin2(__hmax2(x1, e0), x4);
        w[1][4] = x2; w[1][5] = x3; w[1][7] = __hmin2(__hmax2(x1, e1), x4);
    }
    // ---- Row 3: bottom-3 set of 5. ----
    {
        __half2 x1 = col1[3], x4 = col4[3];
        __half2 x2 = midcol(col0[3], col4[3]);
        __half2 x3 = midcol(col1[3], col5[3]);
        cas2(x1, x2); cas2(x3, x4);
        __half2 z = __hmin2(x2, x4);
        __half2 m = __hmin2(x1, x3), M = __hmax2(x1, x3);
        __half2 e0 = col0[3], e1 = col5[3];
        s[0][0] = m; s[0][1] = __hmin2(z, e0); s[0][2] = __hmin2(M, __hmax2(z, e0));
        s[1][0] = m; s[1][1] = __hmin2(z, e1); s[1][2] = __hmin2(M, __hmax2(z, e1));
    }
    // ---- Row 4 (column maxima): bottom-2 set of 5. ----
    {
        __half2 x1 = col1[4], x4 = col4[4];
        __half2 x2 = midcol(col0[4], col4[4]);
        __half2 x3 = midcol(col1[4], col5[4]);
        cas2(x1, x2); cas2(x3, x4);
        __half2 B1 = __hmin2(x1, x3);
        __half2 B2 = __hmin2(__hmax2(x1, x3), __hmin2(x2, x4));
        __half2 e0 = col0[4], e1 = col5[4];
        s[0][3] = __hmin2(B1, e0); s[0][4] = __hmin2(B2, __hmax2(B1, e0));
        s[1][3] = __hmin2(B1, e1); s[1][4] = __hmin2(B2, __hmax2(B1, e1));
    }

    // Forgetful selection: median = rank 7 (1-indexed) of the 13 candidates.
    __half2 res[2];
    #pragma unroll
    for (int g = 0; g < 2; g++) {
        __half2 w0 = w[g][0], w1 = w[g][1], w2 = w[g][2], w3 = w[g][3];
        __half2 w4 = w[g][4], w5 = w[g][5], w6 = w[g][6], w7 = w[g][7];

        // minmax8 (tree); (w0,w1),(w2,w3),(w4,w5) pre-ordered -> 7 CAS.
        cas2(w6, w7);
        cas2(w0, w2); cas2(w4, w6); cas2(w0, w4);   // w0 = min8
        cas2(w1, w3); cas2(w5, w7); cas2(w3, w7);   // w7 = max8
        w0 = s[g][0];
        // minmax7: survivors w1..w5.
        cas2(w0, w1); cas2(w2, w3); cas2(w4, w5);
        cas2(w0, w2); cas2(w4, w6); cas2(w0, w4);
        cas2(w1, w3); cas2(w5, w6); cas2(w3, w6);
        w0 = s[g][1];
        // minmax6: survivors w1..w4.
        cas2(w0, w1); cas2(w2, w3); cas2(w4, w5);
        cas2(w0, w2); cas2(w0, w4);
        cas2(w1, w3); cas2(w3, w5);
        w0 = s[g][2];
        // minmax5: survivors w1, w2, w4.
        cas2(w0, w1); cas2(w2, w3); cas2(w0, w2); cas2(w1, w3); cas2(w0, w4); cas2(w4, w3);
        w0 = s[g][3];
        // minmax4 on (w0, w1, w2, w4): survivors w1, w2.
        cas2(w0, w1); cas2(w2, w4); cas2(w0, w2); cas2(w1, w4);
        // med3(s4, w1, w2) via 4-op identity.
        __half2 a = s[g][4];
        res[g] = __hmax2(__hmin2(a, w1), __hmin2(__hmax2(a, w1), w2));
    }

    // Unpack: pair0 = pixels (0,2), pair1 = pixels (1,3).
    float2 p0 = __half22float2(res[0]);
    float2 p1 = __half22float2(res[1]);
    float4 r4 = make_float4(p0.x, p1.x, p0.y, p1.y);

    const int gy = by + ty;
    *reinterpret_cast<float4*>(&dst[gy * IMG + bx + tx * PPT]) = r4;
}

extern "C" void kernel_launch(void* const* d_in, const int* in_sizes, int n_in,
                              void* d_out, int out_size) {
    const float* image = (const float*)d_in[0];
    float* out = (float*)d_out;
    (void)in_sizes; (void)n_in; (void)out_size;

    dim3 block(BX, BY);
    dim3 grid(IMG / OUT_W, IMG / OUT_H, 16 * 3);
    median5_kernel<<<grid, block>>>(image, out);
}

// round 16
// speedup vs baseline: 1.0263x; 1.0155x over previous
#include <cuda_runtime.h>
#include <cuda_fp16.h>

// 5x5 median filter, reflect padding, [16,3,256,256] fp32.
//
// fp16x2 packed median, stride-2 packing P[c] = (v[c], v[c+2]) for
// c%4 in {0,1} only.  Vectorized group loader (r15): interior groups load
// 4 contiguous floats (2x LDG.64 + 2x F2FP + STS.64), edges scalar-reflect.
// Compute: PRMT column dedup (r13), shared-4 selections + tournament
// extensions (r6), triple-elided forgetful rank-7-of-13 (r14).
// Round 16: __launch_bounds__(256, 8) -> 32 regs, 64 warps/SM target
// (was 34 regs / 48 warps); only 2 regs to shave, expect rematerialization
// not spills.

#define BX 16
#define BY 16
#define PPT 4
#define OUT_W (BX * PPT)        // 64
#define OUT_H BY                // 16
#define PAD 2
#define TILE_W (OUT_W + 2*PAD)  // 68 source columns
#define TILE_H (OUT_H + 2*PAD)  // 20
#define PROW 68                 // packed-row stride in half2 (272B = 17*16B)
#define IMG 256

__device__ __forceinline__ void cas2(__half2& a, __half2& b) {
    __half2 lo = __hmin2(a, b);
    __half2 hi = __hmax2(a, b);
    a = lo;
    b = hi;
}

// Optimal 9-CAS sorting network for 5 elements (packed).
__device__ __forceinline__ void sort5p(__half2& a, __half2& b, __half2& c,
                                       __half2& d, __half2& e) {
    cas2(a, b); cas2(d, e); cas2(c, e); cas2(c, d); cas2(b, e);
    cas2(a, d); cas2(a, c); cas2(b, d); cas2(b, c);
}

// (a.y, b.x) as a half2 — lane-wise column recombination (exact bit-moves).
__device__ __forceinline__ __half2 midcol(__half2 a, __half2 b) {
    unsigned int r = __byte_perm(*reinterpret_cast<unsigned int*>(&a),
                                 *reinterpret_cast<unsigned int*>(&b), 0x5432);
    return *reinterpret_cast<__half2*>(&r);
}

// Branch-free reflect for pad<=2 on [0,255]: -2->2, -1->1, 256->254, 257->253.
__device__ __forceinline__ int refl255(int x) {
    return 255 - abs(255 - abs(x));
}

// Store packed group g (tile cols 4g..4g+3) for tile row r from 4 floats.
__device__ __forceinline__ void store_group(__half2 (*P)[PROW], int r, int g,
                                            float f0, float f1, float f2, float f3) {
    __half2 h0 = __floats2half2_rn(f0, f2);   // P[r][4g]   = (v[4g],   v[4g+2])
    __half2 h1 = __floats2half2_rn(f1, f3);   // P[r][4g+1] = (v[4g+1], v[4g+3])
    uint2 st = make_uint2(*reinterpret_cast<unsigned int*>(&h0),
                          *reinterpret_cast<unsigned int*>(&h1));
    *reinterpret_cast<uint2*>(&P[r][4 * g]) = st;
}

__global__ __launch_bounds__(BX * BY, 8) void median5_kernel(
    const float* __restrict__ in, float* __restrict__ out) {
    // Packed tile: P[r][c] = (half v[c], half v[c+2]) for c%4 in {0,1}.
    __shared__ __half2 P[TILE_H][PROW];

    const int plane = blockIdx.z;  // 48 planes
    const float* src = in + (size_t)plane * IMG * IMG;
    float* dst = out + (size_t)plane * IMG * IMG;

    const int bx = blockIdx.x * OUT_W;
    const int by = blockIdx.y * OUT_H;
    const int tx = threadIdx.x;
    const int ty = threadIdx.y;

    // ---- Vectorized group loader ----
    {
        const bool edgeL = (bx == 0);
        const bool edgeR = (bx + OUT_W == IMG);
        const int gy0 = refl255(by + ty - PAD);
        const int gy1 = refl255(by + ty + 16 - PAD);

        #pragma unroll
        for (int j = 0; j < 2; j++) {
            if (j == 1 && ty >= TILE_H - 16) break;  // r < 20
            const int r = ty + 16 * j;
            const float* rowsrc = src + (j == 0 ? gy0 : gy1) * IMG;

            // main group g = tx
            if (tx == 0 && edgeL) {
                store_group(P, r, 0, rowsrc[2], rowsrc[1], rowsrc[0], rowsrc[1]);
            } else {
                const float* p = rowsrc + bx + 4 * tx - PAD;
                float2 a = *reinterpret_cast<const float2*>(p);
                float2 b = *reinterpret_cast<const float2*>(p + 2);
                store_group(P, r, tx, a.x, a.y, b.x, b.y);
            }
            // extra group g = 16 (tile cols 64..67)
            if (tx == 0) {
                if (edgeR) {
                    store_group(P, r, 16, rowsrc[254], rowsrc[255],
                                rowsrc[254], rowsrc[253]);
                } else {
                    const float* p = rowsrc + bx + 64 - PAD;
                    float2 a = *reinterpret_cast<const float2*>(p);
                    float2 b = *reinterpret_cast<const float2*>(p + 2);
                    store_group(P, r, 16, a.x, a.y, b.x, b.y);
                }
            }
        }
    }
    __syncthreads();

    // Read packed cols 0,1,4,5 (two LDS.64 per row), sort each once.
    __half2 col0[5], col1[5], col4[5], col5[5];
    #pragma unroll
    for (int r = 0; r < 5; r++) {
        const __half2* rowp = &P[ty + r][tx * PPT];
        uint2 qa = *reinterpret_cast<const uint2*>(rowp);
        uint2 qb = *reinterpret_cast<const uint2*>(rowp + 4);
        col0[r] = *reinterpret_cast<__half2*>(&qa.x);
        col1[r] = *reinterpret_cast<__half2*>(&qa.y);
        col4[r] = *reinterpret_cast<__half2*>(&qb.x);
        col5[r] = *reinterpret_cast<__half2*>(&qb.y);
    }
    sort5p(col0[0], col0[1], col0[2], col0[3], col0[4]);
    sort5p(col1[0], col1[1], col1[2], col1[3], col1[4]);
    sort5p(col4[0], col4[1], col4[2], col4[3], col4[4]);
    sort5p(col5[0], col5[1], col5[2], col5[3], col5[4]);

    // Candidate sets for the two pairs (pair 0: cols 0..4, pair 1: cols 1..5).
    // Slot layout (triple-elided minmax8 — three pre-sorted pairs):
    //   w0<=w1 : row0 (2nd max, max)
    //   w2<=w3 : row1 (third-of-top3, mx)
    //   w4<=w5 : row2 mids (x2,x3) after shared cas
    //   w6,w7  : row1 max(y,e), row2 extension (unordered)
    __half2 w[2][8], s[2][5];

    // ---- Row 0 (column minima): top-2 set of 5. ----
    {
        __half2 x1 = col1[0], x4 = col4[0];
        __half2 x2 = midcol(col0[0], col4[0]);
        __half2 x3 = midcol(col1[0], col5[0]);
        cas2(x1, x2); cas2(x3, x4);
        __half2 T1 = __hmax2(x2, x4);
        __half2 T2 = __hmax2(__hmin2(x2, x4), __hmax2(x1, x3));
        __half2 e0 = col0[0], e1 = col5[0];
        w[0][1] = __hmax2(T1, e0); w[0][0] = __hmax2(T2, __hmin2(T1, e0));
        w[1][1] = __hmax2(T1, e1); w[1][0] = __hmax2(T2, __hmin2(T1, e1));
    }
    // ---- Row 1: top-3 set of 5: {third, mx, max(y,e)}. ----
    {
        __half2 x1 = col1[1], x4 = col4[1];
        __half2 x2 = midcol(col0[1], col4[1]);
        __half2 x3 = midcol(col1[1], col5[1]);
        cas2(x1, x2); cas2(x3, x4);
        __half2 y  = __hmax2(x1, x3);
        __half2 mx = __hmax2(x2, x4), mn = __hmin2(x2, x4);
        __half2 e0 = col0[1], e1 = col5[1];
        w[0][3] = mx; w[0][6] = __hmax2(y, e0); w[0][2] = __hmax2(mn, __hmin2(y, e0));
        w[1][3] = mx; w[1][6] = __hmax2(y, e1); w[1][2] = __hmax2(mn, __hmin2(y, e1));
    }
    // ---- Row 2 (column medians): middle-3 set of 5; mids pre-sorted. ----
    {
        __half2 x1 = col1[2], x4 = col4[2];
        __half2 x2 = midcol(col0[2], col4[2]);
        __half2 x3 = midcol(col1[2], col5[2]);
        cas2(x1, x2); cas2(x3, x4); cas2(x1, x3); cas2(x2, x4);
        cas2(x2, x3);  // shared: (x2,x3) sorted for both pairs
        __half2 e0 = col0[2], e1 = col5[2];
        w[0][4] = x2; w[0][5] = x3; w[0][7] = __hmin2(__hmax2(x1, e0), x4);
        w[1][4] = x2; w[1][5] = x3; w[1][7] = __hmin2(__hmax2(x1, e1), x4);
    }
    // ---- Row 3: bottom-3 set of 5. ----
    {
        __half2 x1 = col1[3], x4 = col4[3];
        __half2 x2 = midcol(col0[3], col4[3]);
        __half2 x3 = midcol(col1[3], col5[3]);
        cas2(x1, x2); cas2(x3, x4);
        __half2 z = __hmin2(x2, x4);
        __half2 m = __hmin2(x1, x3), M = __hmax2(x1, x3);
        __half2 e0 = col0[3], e1 = col5[3];
        s[0][0] = m; s[0][1] = __hmin2(z, e0); s[0][2] = __hmin2(M, __hmax2(z, e0));
        s[1][0] = m; s[1][1] = __hmin2(z, e1); s[1][2] = __hmin2(M, __hmax2(z, e1));
    }
    // ---- Row 4 (column maxima): bottom-2 set of 5. ----
    {
        __half2 x1 = col1[4], x4 = col4[4];
        __half2 x2 = midcol(col0[4], col4[4]);
        __half2 x3 = midcol(col1[4], col5[4]);
        cas2(x1, x2); cas2(x3, x4);
        __half2 B1 = __hmin2(x1, x3);
        __half2 B2 = __hmin2(__hmax2(x1, x3), __hmin2(x2, x4));
        __half2 e0 = col0[4], e1 = col5[4];
        s[0][3] = __hmin2(B1, e0); s[0][4] = __hmin2(B2, __hmax2(B1, e0));
        s[1][3] = __hmin2(B1, e1); s[1][4] = __hmin2(B2, __hmax2(B1, e1));
    }

    // Forgetful selection: median = rank 7 (1-indexed) of the 13 candidates.
    __half2 res[2];
    #pragma unroll
    for (int g = 0; g < 2; g++) {
        __half2 w0 = w[g][0], w1 = w[g][1], w2 = w[g][2], w3 = w[g][3];
        __half2 w4 = w[g][4], w5 = w[g][5], w6 = w[g][6], w7 = w[g][7];

        // minmax8 (tree); (w0,w1),(w2,w3),(w4,w5) pre-ordered -> 7 CAS.
        cas2(w6, w7);
        cas2(w0, w2); cas2(w4, w6); cas2(w0, w4);   // w0 = min8
        cas2(w1, w3); cas2(w5, w7); cas2(w3, w7);   // w7 = max8
        w0 = s[g][0];
        // minmax7: survivors w1..w5.
        cas2(w0, w1); cas2(w2, w3); cas2(w4, w5);
        cas2(w0, w2); cas2(w4, w6); cas2(w0, w4);
        cas2(w1, w3); cas2(w5, w6); cas2(w3, w6);
        w0 = s[g][1];
        // minmax6: survivors w1..w4.
        cas2(w0, w1); cas2(w2, w3); cas2(w4, w5);
        cas2(w0, w2); cas2(w0, w4);
        cas2(w1, w3); cas2(w3, w5);
        w0 = s[g][2];
        // minmax5: survivors w1, w2, w4.
        cas2(w0, w1); cas2(w2, w3); cas2(w0, w2); cas2(w1, w3); cas2(w0, w4); cas2(w4, w3);
        w0 = s[g][3];
        // minmax4 on (w0, w1, w2, w4): survivors w1, w2.
        cas2(w0, w1); cas2(w2, w4); cas2(w0, w2); cas2(w1, w4);
        // med3(s4, w1, w2) via 4-op identity.
        __half2 a = s[g][4];
        res[g] = __hmax2(__hmin2(a, w1), __hmin2(__hmax2(a, w1), w2));
    }

    // Unpack: pair0 = pixels (0,2), pair1 = pixels (1,3).
    float2 p0 = __half22float2(res[0]);
    float2 p1 = __half22float2(res[1]);
    float4 r4 = make_float4(p0.x, p1.x, p0.y, p1.y);

    const int gy = by + ty;
    *reinterpret_cast<float4*>(&dst[gy * IMG + bx + tx * PPT]) = r4;
}

extern "C" void kernel_launch(void* const* d_in, const int* in_sizes, int n_in,
                              void* d_out, int out_size) {
    const float* image = (const float*)d_in[0];
    float* out = (float*)d_out;
    (void)in_sizes; (void)n_in; (void)out_size;

    dim3 block(BX, BY);
    dim3 grid(IMG / OUT_W, IMG / OUT_H, 16 * 3);
    median5_kernel<<<grid, block>>>(image, out);
}

// round 17
// speedup vs baseline: 1.0608x; 1.0336x over previous
#include <cuda_runtime.h>
#include <cuda_fp16.h>

// 5x5 median filter, reflect padding, [16,3,256,256] fp32.
//
// fp16x2 packed median, stride-2 packing P[c] = (v[c], v[c+2]) for
// c%4 in {0,1} only (34 packed cols per row; each scalar stored once).
// Round 17: r14 uniform packed-slot loader (balanced warps, best issue
// rate) combined with r16's __launch_bounds__(256,8) (32 regs, 64 warps/SM
// target, 82.8% achieved occ).  Compute unchanged: PRMT column dedup (r13),
// shared-4 selections + tournament extensions (r6), triple-elided
// forgetful rank-7-of-13 (r14).

#define BX 16
#define BY 16
#define PPT 4
#define OUT_W (BX * PPT)        // 64
#define OUT_H BY                // 16
#define PAD 2
#define TILE_W (OUT_W + 2*PAD)  // 68 source columns
#define TILE_H (OUT_H + 2*PAD)  // 20
#define PROW 68                 // packed-row stride in half2 (272B = 17*16B)
#define NPC 34                  // packed cols per row
#define IMG 256

__device__ __forceinline__ void cas2(__half2& a, __half2& b) {
    __half2 lo = __hmin2(a, b);
    __half2 hi = __hmax2(a, b);
    a = lo;
    b = hi;
}

// Optimal 9-CAS sorting network for 5 elements (packed).
__device__ __forceinline__ void sort5p(__half2& a, __half2& b, __half2& c,
                                       __half2& d, __half2& e) {
    cas2(a, b); cas2(d, e); cas2(c, e); cas2(c, d); cas2(b, e);
    cas2(a, d); cas2(a, c); cas2(b, d); cas2(b, c);
}

// (a.y, b.x) as a half2 — lane-wise column recombination (exact bit-moves).
__device__ __forceinline__ __half2 midcol(__half2 a, __half2 b) {
    unsigned int r = __byte_perm(*reinterpret_cast<unsigned int*>(&a),
                                 *reinterpret_cast<unsigned int*>(&b), 0x5432);
    return *reinterpret_cast<__half2*>(&r);
}

// Branch-free reflect for pad<=2 on [0,255]: -2->2, -1->1, 256->254, 257->253.
__device__ __forceinline__ int refl255(int x) {
    return 255 - abs(255 - abs(x));
}

__global__ __launch_bounds__(BX * BY, 8) void median5_kernel(
    const float* __restrict__ in, float* __restrict__ out) {
    // Packed tile: P[r][c] = (half v[c], half v[c+2]) for c%4 in {0,1}.
    __shared__ __half2 P[TILE_H][PROW];

    const int plane = blockIdx.z;  // 48 planes
    const float* src = in + (size_t)plane * IMG * IMG;
    float* dst = out + (size_t)plane * IMG * IMG;

    const int bx = blockIdx.x * OUT_W;
    const int by = blockIdx.y * OUT_H;
    const int tx = threadIdx.x;
    const int ty = threadIdx.y;

    // ---- Packed-slot halo loader (uniform across lanes) ----
    // Packed col slots cp = tx, tx+16, (tx<2: tx+32); c = 4*(cp>>1)+(cp&1).
    // Slot (r, cp): P[r][c] = (v[c], v[c+2]) via 2x LDG.32 + F2FP + STS.32.
    // Row slots r = ty + 16j, j=0,1 (j=1 iff ty<4).
    {
        int cs[3], gx0[3], gx2[3];
        #pragma unroll
        for (int k = 0; k < 3; k++) {
            int cp = tx + 16 * k;
            int c = 4 * (cp >> 1) + (cp & 1);
            cs[k] = c;
            gx0[k] = refl255(bx + c - PAD);
            gx2[k] = refl255(bx + c + 2 - PAD);
        }
        int gy0 = refl255(by + ty - PAD);
        int gy1 = refl255(by + ty + 16 - PAD);

        #pragma unroll
        for (int j = 0; j < 2; j++) {
            if (j == 1 && ty >= TILE_H - 16) break;  // r < 20
            int r = ty + 16 * j;
            const float* rowsrc = src + (j == 0 ? gy0 : gy1) * IMG;
            #pragma unroll
            for (int k = 0; k < 3; k++) {
                if (k == 2 && tx >= NPC - 32) break;  // cp < 34
                P[r][cs[k]] = __floats2half2_rn(rowsrc[gx0[k]], rowsrc[gx2[k]]);
            }
        }
    }
    __syncthreads();

    // Read packed cols 0,1,4,5 (two LDS.64 per row), sort each once.
    __half2 col0[5], col1[5], col4[5], col5[5];
    #pragma unroll
    for (int r = 0; r < 5; r++) {
        const __half2* rowp = &P[ty + r][tx * PPT];
        uint2 qa = *reinterpret_cast<const uint2*>(rowp);
        uint2 qb = *reinterpret_cast<const uint2*>(rowp + 4);
        col0[r] = *reinterpret_cast<__half2*>(&qa.x);
        col1[r] = *reinterpret_cast<__half2*>(&qa.y);
        col4[r] = *reinterpret_cast<__half2*>(&qb.x);
        col5[r] = *reinterpret_cast<__half2*>(&qb.y);
    }
    sort5p(col0[0], col0[1], col0[2], col0[3], col0[4]);
    sort5p(col1[0], col1[1], col1[2], col1[3], col1[4]);
    sort5p(col4[0], col4[1], col4[2], col4[3], col4[4]);
    sort5p(col5[0], col5[1], col5[2], col5[3], col5[4]);

    // Candidate sets for the two pairs (pair 0: cols 0..4, pair 1: cols 1..5).
    // Slot layout (triple-elided minmax8 — three pre-sorted pairs):
    //   w0<=w1 : row0 (2nd max, max)
    //   w2<=w3 : row1 (third-of-top3, mx)
    //   w4<=w5 : row2 mids (x2,x3) after shared cas
    //   w6,w7  : row1 max(y,e), row2 extension (unordered)
    __half2 w[2][8], s[2][5];

    // ---- Row 0 (column minima): top-2 set of 5. ----
    {
        __half2 x1 = col1[0], x4 = col4[0];
        __half2 x2 = midcol(col0[0], col4[0]);
        __half2 x3 = midcol(col1[0], col5[0]);
        cas2(x1, x2); cas2(x3, x4);
        __half2 T1 = __hmax2(x2, x4);
        __half2 T2 = __hmax2(__hmin2(x2, x4), __hmax2(x1, x3));
        __half2 e0 = col0[0], e1 = col5[0];
        w[0][1] = __hmax2(T1, e0); w[0][0] = __hmax2(T2, __hmin2(T1, e0));
        w[1][1] = __hmax2(T1, e1); w[1][0] = __hmax2(T2, __hmin2(T1, e1));
    }
    // ---- Row 1: top-3 set of 5: {third, mx, max(y,e)}. ----
    {
        __half2 x1 = col1[1], x4 = col4[1];
        __half2 x2 = midcol(col0[1], col4[1]);
        __half2 x3 = midcol(col1[1], col5[1]);
        cas2(x1, x2); cas2(x3, x4);
        __half2 y  = __hmax2(x1, x3);
        __half2 mx = __hmax2(x2, x4), mn = __hmin2(x2, x4);
        __half2 e0 = col0[1], e1 = col5[1];
        w[0][3] = mx; w[0][6] = __hmax2(y, e0); w[0][2] = __hmax2(mn, __hmin2(y, e0));
        w[1][3] = mx; w[1][6] = __hmax2(y, e1); w[1][2] = __hmax2(mn, __hmin2(y, e1));
    }
    // ---- Row 2 (column medians): middle-3 set of 5; mids pre-sorted. ----
    {
        __half2 x1 = col1[2], x4 = col4[2];
        __half2 x2 = midcol(col0[2], col4[2]);
        __half2 x3 = midcol(col1[2], col5[2]);
        cas2(x1, x2); cas2(x3, x4); cas2(x1, x3); cas2(x2, x4);
        cas2(x2, x3);  // shared: (x2,x3) sorted for both pairs
        __half2 e0 = col0[2], e1 = col5[2];
        w[0][4] = x2; w[0][5] = x3; w[0][7] = __hmin2(__hmax2(x1, e0), x4);
        w[1][4] = x2; w[1][5] = x3; w[1][7] = __hmin2(__hmax2(x1, e1), x4);
    }
    // ---- Row 3: bottom-3 set of 5. ----
    {
        __half2 x1 = col1[3], x4 = col4[3];
        __half2 x2 = midcol(col0[3], col4[3]);
        __half2 x3 = midcol(col1[3], col5[3]);
        cas2(x1, x2); cas2(x3, x4);
        __half2 z = __hmin2(x2, x4);
        __half2 m = __hmin2(x1, x3), M = __hmax2(x1, x3);
        __half2 e0 = col0[3], e1 = col5[3];
        s[0][0] = m; s[0][1] = __hmin2(z, e0); s[0][2] = __hmin2(M, __hmax2(z, e0));
        s[1][0] = m; s[1][1] = __hmin2(z, e1); s[1][2] = __hmin2(M, __hmax2(z, e1));
    }
    // ---- Row 4 (column maxima): bottom-2 set of 5. ----
    {
        __half2 x1 = col1[4], x4 = col4[4];
        __half2 x2 = midcol(col0[4], col4[4]);
        __half2 x3 = midcol(col1[4], col5[4]);
        cas2(x1, x2); cas2(x3, x4);
        __half2 B1 = __hmin2(x1, x3);
        __half2 B2 = __hmin2(__hmax2(x1, x3), __hmin2(x2, x4));
        __half2 e0 = col0[4], e1 = col5[4];
        s[0][3] = __hmin2(B1, e0); s[0][4] = __hmin2(B2, __hmax2(B1, e0));
        s[1][3] = __hmin2(B1, e1); s[1][4] = __hmin2(B2, __hmax2(B1, e1));
    }

    // Forgetful selection: median = rank 7 (1-indexed) of the 13 candidates.
    __half2 res[2];
    #pragma unroll
    for (int g = 0; g < 2; g++) {
        __half2 w0 = w[g][0], w1 = w[g][1], w2 = w[g][2], w3 = w[g][3];
        __half2 w4 = w[g][4], w5 = w[g][5], w6 = w[g][6], w7 = w[g][7];

        // minmax8 (tree); (w0,w1),(w2,w3),(w4,w5) pre-ordered -> 7 CAS.
        cas2(w6, w7);
        cas2(w0, w2); cas2(w4, w6); cas2(w0, w4);   // w0 = min8
        cas2(w1, w3); cas2(w5, w7); cas2(w3, w7);   // w7 = max8
        w0 = s[g][0];
        // minmax7: survivors w1..w5.
        cas2(w0, w1); cas2(w2, w3); cas2(w4, w5);
        cas2(w0, w2); cas2(w4, w6); cas2(w0, w4);
        cas2(w1, w3); cas2(w5, w6); cas2(w3, w6);
        w0 = s[g][1];
        // minmax6: survivors w1..w4.
        cas2(w0, w1); cas2(w2, w3); cas2(w4, w5);
        cas2(w0, w2); cas2(w0, w4);
        cas2(w1, w3); cas2(w3, w5);
        w0 = s[g][2];
        // minmax5: survivors w1, w2, w4.
        cas2(w0, w1); cas2(w2, w3); cas2(w0, w2); cas2(w1, w3); cas2(w0, w4); cas2(w4, w3);
        w0 = s[g][3];
        // minmax4 on (w0, w1, w2, w4): survivors w1, w2.
        cas2(w0, w1); cas2(w2, w4); cas2(w0, w2); cas2(w1, w4);
        // med3(s4, w1, w2) via 4-op identity.
        __half2 a = s[g][4];
        res[g] = __hmax2(__hmin2(a, w1), __hmin2(__hmax2(a, w1), w2));
    }

    // Unpack: pair0 = pixels (0,2), pair1 = pixels (1,3).
    float2 p0 = __half22float2(res[0]);
    float2 p1 = __half22float2(res[1]);
    float4 r4 = make_float4(p0.x, p1.x, p0.y, p1.y);

    const int gy = by + ty;
    *reinterpret_cast<float4*>(&dst[gy * IMG + bx + tx * PPT]) = r4;
}

extern "C" void kernel_launch(void* const* d_in, const int* in_sizes, int n_in,
                              void* d_out, int out_size) {
    const float* image = (const float*)d_in[0];
    float* out = (float*)d_out;
    (void)in_sizes; (void)n_in; (void)out_size;

    dim3 block(BX, BY);
    dim3 grid(IMG / OUT_W, IMG / OUT_H, 16 * 3);
    median5_kernel<<<grid, block>>>(image, out);
}